// round 1
// baseline (speedup 1.0000x reference)
#include <cuda_runtime.h>
#include <cuda_bf16.h>
#include <cstdint>

// ---------------------------------------------------------------------------
// Problem constants (fixed by setup_inputs)
// ---------------------------------------------------------------------------
#define D          128
#define N0_NODES   1081344
#define N1_NODES   67584
#define N2_NODES   6144
#define N3_NODES   1024
#define F0         15
#define F1         10
#define F2         5

// Scratch buffers (no cudaMalloc allowed)
__device__ float g_agg[N1_NODES * D];     // reused across layers (max size)
__device__ float g_h1 [N1_NODES * D];
__device__ float g_h2 [N2_NODES * D];
__device__ float g_logits[N3_NODES * D];

// ---------------------------------------------------------------------------
// Aggregation: warp per target, mean of F gathered rows (rows are 512B, one
// float4 per lane). F templated so the gather loop fully unrolls -> MLP = F.
// ---------------------------------------------------------------------------
template <int F>
__global__ void __launch_bounds__(256) agg_kernel(
    const float* __restrict__ x, const int* __restrict__ src,
    float* __restrict__ agg, int nt)
{
    int warp = blockIdx.x * 8 + (threadIdx.x >> 5);
    int lane = threadIdx.x & 31;
    if (warp >= nt) return;

    const float4* xv = reinterpret_cast<const float4*>(x);
    const int* sp = src + warp * F;

    int rows[F];
#pragma unroll
    for (int j = 0; j < F; j++) rows[j] = __ldg(sp + j);

    float4 s = make_float4(0.f, 0.f, 0.f, 0.f);
#pragma unroll
    for (int j = 0; j < F; j++) {
        float4 v = __ldg(&xv[(long)rows[j] * 32 + lane]);
        s.x += v.x; s.y += v.y; s.z += v.z; s.w += v.w;
    }
    const float invf = 1.0f / (float)F;
    s.x *= invf; s.y *= invf; s.z *= invf; s.w *= invf;
    reinterpret_cast<float4*>(agg)[(long)warp * 32 + lane] = s;
}

// ---------------------------------------------------------------------------
// Fused dual GEMM:  out[M,128] = Agg[M,128] @ Wl^T + X[M,128] @ Wr^T
// Treated as a single M x 128 x 256 GEMM (A = [Agg | X], B = [Wl ; Wr]^T)
// using tf32 mma.sync.m16n8k8.  M is always a multiple of 64.
// relu != 0 applies ReLU in the epilogue.
// ---------------------------------------------------------------------------
__device__ __forceinline__ uint32_t f2tf32(float f) {
    uint32_t r;
    asm volatile("cvt.rna.tf32.f32 %0, %1;" : "=r"(r) : "f"(f));
    return r;
}

__device__ __forceinline__ void mma_tf32(float c[4], const uint32_t a[4],
                                         const uint32_t b[2]) {
    asm volatile(
        "mma.sync.aligned.m16n8k8.row.col.f32.tf32.tf32.f32 "
        "{%0,%1,%2,%3}, {%4,%5,%6,%7}, {%8,%9}, {%0,%1,%2,%3};"
        : "+f"(c[0]), "+f"(c[1]), "+f"(c[2]), "+f"(c[3])
        : "r"(a[0]), "r"(a[1]), "r"(a[2]), "r"(a[3]), "r"(b[0]), "r"(b[1]));
}

__global__ void __launch_bounds__(256) gemm_dual_kernel(
    const float* __restrict__ Aagg, const float* __restrict__ X,
    const float* __restrict__ Wl,   const float* __restrict__ Wr,
    float* __restrict__ out, int relu)
{
    __shared__ uint32_t As[64][36];    // [m][k] tile, padded
    __shared__ uint32_t Bs[32][132];   // [k][n] tile, padded

    const int tid  = threadIdx.x;
    const int lane = tid & 31;
    const int wid  = tid >> 5;          // 8 warps
    const int wm   = wid & 1;           // warp row  (2 x 32 rows)
    const int wn   = wid >> 1;          // warp col  (4 x 32 cols)
    const int grp  = lane >> 2;         // 0..7
    const int tg   = lane & 3;          // 0..3
    const long blockM = (long)blockIdx.x * 64;

    float acc[2][4][4];
#pragma unroll
    for (int mi = 0; mi < 2; mi++)
#pragma unroll
        for (int ni = 0; ni < 4; ni++)
#pragma unroll
            for (int q = 0; q < 4; q++) acc[mi][ni][q] = 0.f;

#pragma unroll 1
    for (int k0 = 0; k0 < 256; k0 += 32) {
        // A tile: 64x32, coalesced along k
#pragma unroll
        for (int i = 0; i < 8; i++) {
            int idx = i * 256 + tid;
            int r = idx >> 5, kk = idx & 31;
            int gk = k0 + kk;
            const float* p = (gk < 128)
                ? (Aagg + (blockM + r) * 128 + gk)
                : (X    + (blockM + r) * 128 + (gk - 128));
            As[r][kk] = f2tf32(__ldg(p));
        }
        // B tile: read W rows coalesced along k, store transposed [k][n]
#pragma unroll
        for (int i = 0; i < 16; i++) {
            int idx = i * 256 + tid;
            int n = idx >> 5, kk = idx & 31;
            int gk = k0 + kk;
            float v = (gk < 128) ? __ldg(Wl + n * 128 + gk)
                                 : __ldg(Wr + n * 128 + (gk - 128));
            Bs[kk][n] = f2tf32(v);
        }
        __syncthreads();

#pragma unroll
        for (int kb = 0; kb < 32; kb += 8) {
            uint32_t af[2][4], bf[4][2];
#pragma unroll
            for (int mi = 0; mi < 2; mi++) {
                int r = wm * 32 + mi * 16;
                af[mi][0] = As[r + grp    ][kb + tg    ];
                af[mi][1] = As[r + grp + 8][kb + tg    ];
                af[mi][2] = As[r + grp    ][kb + tg + 4];
                af[mi][3] = As[r + grp + 8][kb + tg + 4];
            }
#pragma unroll
            for (int ni = 0; ni < 4; ni++) {
                int c = wn * 32 + ni * 8;
                bf[ni][0] = Bs[kb + tg    ][c + grp];
                bf[ni][1] = Bs[kb + tg + 4][c + grp];
            }
#pragma unroll
            for (int mi = 0; mi < 2; mi++)
#pragma unroll
                for (int ni = 0; ni < 4; ni++)
                    mma_tf32(acc[mi][ni], af[mi], bf[ni]);
        }
        __syncthreads();
    }

    // Epilogue
#pragma unroll
    for (int mi = 0; mi < 2; mi++) {
#pragma unroll
        for (int ni = 0; ni < 4; ni++) {
            long row = blockM + wm * 32 + mi * 16 + grp;
            int  col = wn * 32 + ni * 8 + tg * 2;
            float c0 = acc[mi][ni][0], c1 = acc[mi][ni][1];
            float c2 = acc[mi][ni][2], c3 = acc[mi][ni][3];
            if (relu) {
                c0 = fmaxf(c0, 0.f); c1 = fmaxf(c1, 0.f);
                c2 = fmaxf(c2, 0.f); c3 = fmaxf(c3, 0.f);
            }
            out[row * 128 + col]           = c0;
            out[row * 128 + col + 1]       = c1;
            out[(row + 8) * 128 + col]     = c2;
            out[(row + 8) * 128 + col + 1] = c3;
        }
    }
}

// ---------------------------------------------------------------------------
// log_softmax over rows of [1024, 128]: one warp per row (4 floats per lane)
// ---------------------------------------------------------------------------
__global__ void __launch_bounds__(256) lsm_kernel(
    const float* __restrict__ in, float* __restrict__ out)
{
    int row  = blockIdx.x * 8 + (threadIdx.x >> 5);
    int lane = threadIdx.x & 31;
    if (row >= N3_NODES) return;

    float4 v = reinterpret_cast<const float4*>(in)[(long)row * 32 + lane];

    float m = fmaxf(fmaxf(v.x, v.y), fmaxf(v.z, v.w));
#pragma unroll
    for (int o = 16; o > 0; o >>= 1)
        m = fmaxf(m, __shfl_xor_sync(0xFFFFFFFF, m, o));

    float s = expf(v.x - m) + expf(v.y - m) + expf(v.z - m) + expf(v.w - m);
#pragma unroll
    for (int o = 16; o > 0; o >>= 1)
        s += __shfl_xor_sync(0xFFFFFFFF, s, o);

    float lse = m + logf(s);
    float4 r = make_float4(v.x - lse, v.y - lse, v.z - lse, v.w - lse);
    reinterpret_cast<float4*>(out)[(long)row * 32 + lane] = r;
}

// ---------------------------------------------------------------------------
// Launch
// ---------------------------------------------------------------------------
extern "C" void kernel_launch(void* const* d_in, const int* in_sizes, int n_in,
                              void* d_out, int out_size)
{
    const long X_SZ = (long)N0_NODES * D;
    const int  W_SZ = D * D;

    const float* x = nullptr;
    const float* Wl[3] = {nullptr, nullptr, nullptr};
    const float* Wr[3] = {nullptr, nullptr, nullptr};
    const int*   src[3] = {nullptr, nullptr, nullptr};

    if ((long)in_sizes[0] == X_SZ && in_sizes[1] == W_SZ) {
        // reference-signature order: x, Wl0,Wr0,Wl1,Wr1,Wl2,Wr2, src0,dst0,...
        x = (const float*)d_in[0];
        for (int i = 0; i < 3; i++) {
            Wl[i]  = (const float*)d_in[1 + 2 * i];
            Wr[i]  = (const float*)d_in[2 + 2 * i];
            src[i] = (const int*)  d_in[7 + 2 * i];
        }
    } else if ((long)in_sizes[0] == X_SZ) {
        // setup_inputs dict order: x, (src_i, dst_i, Wl_i, Wr_i) x 3
        x = (const float*)d_in[0];
        for (int i = 0; i < 3; i++) {
            src[i] = (const int*)  d_in[1 + 4 * i];
            Wl[i]  = (const float*)d_in[3 + 4 * i];
            Wr[i]  = (const float*)d_in[4 + 4 * i];
        }
    } else {
        // alphabetical: W_l0..2, W_r0..2, dst0..2, src0..2, x
        for (int i = 0; i < 3; i++) {
            Wl[i]  = (const float*)d_in[i];
            Wr[i]  = (const float*)d_in[3 + i];
            src[i] = (const int*)  d_in[9 + i];
        }
        x = (const float*)d_in[12];
    }

    float *agg, *h1, *h2, *logits;
    cudaGetSymbolAddress((void**)&agg,    g_agg);
    cudaGetSymbolAddress((void**)&h1,     g_h1);
    cudaGetSymbolAddress((void**)&h2,     g_h2);
    cudaGetSymbolAddress((void**)&logits, g_logits);

    float* out = (float*)d_out;

    // Layer 0: N0 -> N1
    agg_kernel<F0><<<N1_NODES / 8, 256>>>(x, src[0], agg, N1_NODES);
    gemm_dual_kernel<<<N1_NODES / 64, 256>>>(agg, x, Wl[0], Wr[0], h1, 1);

    // Layer 1: N1 -> N2
    agg_kernel<F1><<<N2_NODES / 8, 256>>>(h1, src[1], agg, N2_NODES);
    gemm_dual_kernel<<<N2_NODES / 64, 256>>>(agg, h1, Wl[1], Wr[1], h2, 1);

    // Layer 2: N2 -> N3
    agg_kernel<F2><<<N3_NODES / 8, 256>>>(h2, src[2], agg, N3_NODES);
    gemm_dual_kernel<<<N3_NODES / 64, 256>>>(agg, h2, Wl[2], Wr[2], logits, 0);

    // log_softmax
    lsm_kernel<<<N3_NODES / 8, 256>>>(logits, out);
}

// round 2
// speedup vs baseline: 1.4031x; 1.4031x over previous
#include <cuda_runtime.h>
#include <cuda_bf16.h>
#include <cstdint>

// ---------------------------------------------------------------------------
// Problem constants (fixed by setup_inputs)
// ---------------------------------------------------------------------------
#define D          128
#define N0_NODES   1081344
#define N1_NODES   67584
#define N2_NODES   6144
#define N3_NODES   1024
#define F0         15
#define F1         10
#define F2         5

// Scratch buffers (no cudaMalloc allowed)
__device__ float g_agg[N1_NODES * D];
__device__ float g_h1 [N1_NODES * D];
__device__ float g_h2 [N2_NODES * D];
__device__ float g_logits[N3_NODES * D];

// ---------------------------------------------------------------------------
// Aggregation: warp per target, mean of F gathered 512B rows.
// (unchanged from round 1 — held as control)
// ---------------------------------------------------------------------------
template <int F>
__global__ void __launch_bounds__(256) agg_kernel(
    const float* __restrict__ x, const int* __restrict__ src,
    float* __restrict__ agg, int nt)
{
    int warp = blockIdx.x * 8 + (threadIdx.x >> 5);
    int lane = threadIdx.x & 31;
    if (warp >= nt) return;

    const float4* xv = reinterpret_cast<const float4*>(x);
    const int* sp = src + warp * F;

    int rows[F];
#pragma unroll
    for (int j = 0; j < F; j++) rows[j] = __ldg(sp + j);

    float4 s = make_float4(0.f, 0.f, 0.f, 0.f);
#pragma unroll
    for (int j = 0; j < F; j++) {
        float4 v = __ldg(&xv[(long)rows[j] * 32 + lane]);
        s.x += v.x; s.y += v.y; s.z += v.z; s.w += v.w;
    }
    const float invf = 1.0f / (float)F;
    s.x *= invf; s.y *= invf; s.z *= invf; s.w *= invf;
    reinterpret_cast<float4*>(agg)[(long)warp * 32 + lane] = s;
}

// ---------------------------------------------------------------------------
// tf32 helpers
// ---------------------------------------------------------------------------
__device__ __forceinline__ uint32_t f2tf32(float f) {
    uint32_t r;
    asm volatile("cvt.rna.tf32.f32 %0, %1;" : "=r"(r) : "f"(f));
    return r;
}

__device__ __forceinline__ void mma_tf32(float c[4], const uint32_t a[4],
                                         const uint32_t b[2]) {
    asm volatile(
        "mma.sync.aligned.m16n8k8.row.col.f32.tf32.tf32.f32 "
        "{%0,%1,%2,%3}, {%4,%5,%6,%7}, {%8,%9}, {%0,%1,%2,%3};"
        : "+f"(c[0]), "+f"(c[1]), "+f"(c[2]), "+f"(c[3])
        : "r"(a[0]), "r"(a[1]), "r"(a[2]), "r"(a[3]), "r"(b[0]), "r"(b[1]));
}

__device__ __forceinline__ void ldsm_x4(uint32_t a[4], uint32_t addr) {
    asm volatile("ldmatrix.sync.aligned.m8n8.x4.shared.b16 {%0,%1,%2,%3}, [%4];"
        : "=r"(a[0]), "=r"(a[1]), "=r"(a[2]), "=r"(a[3]) : "r"(addr));
}
__device__ __forceinline__ void ldsm_x2(uint32_t b[2], uint32_t addr) {
    asm volatile("ldmatrix.sync.aligned.m8n8.x2.shared.b16 {%0,%1}, [%2];"
        : "=r"(b[0]), "=r"(b[1]) : "r"(addr));
}

__device__ __forceinline__ void cp_async16(uint32_t saddr, const void* gptr) {
    asm volatile("cp.async.cg.shared.global [%0], [%1], 16;" ::
                 "r"(saddr), "l"(gptr));
}

// ---------------------------------------------------------------------------
// Fused dual GEMM:  out[M,128] = Agg[M,128] @ Wl^T + X[M,128] @ Wr^T
// Single M x 128 x 256 GEMM, A = [Agg | X], B = [Wl ; Wr] (n-major, k-contig).
// Block tile 128x128, 8 warps (4m x 2n), warp tile 32x64.
// B staged once (tf32), A cp.async double-buffered k-chunks of 64.
// M must be a multiple of 128.
// ---------------------------------------------------------------------------
#define BS_STRIDE 260                       // words per B row (k), padded
#define AS_STRIDE 68                        // words per A row (k-chunk), padded
#define BS_WORDS  (128 * BS_STRIDE)
#define AS_WORDS  (128 * AS_STRIDE)
#define GEMM_SMEM_BYTES ((BS_WORDS + 2 * AS_WORDS) * 4)

__global__ void __launch_bounds__(256, 1) gemm_dual_kernel(
    const float* __restrict__ Aagg, const float* __restrict__ X,
    const float* __restrict__ Wl,   const float* __restrict__ Wr,
    float* __restrict__ out, int relu)
{
    extern __shared__ uint32_t smem[];
    uint32_t* Bs = smem;               // [128 n][260]
    uint32_t* As = smem + BS_WORDS;    // [2][128 m][68]

    const int tid  = threadIdx.x;
    const int lane = tid & 31;
    const int wid  = tid >> 5;
    const int wm   = wid & 3;          // 4 warp rows x 32 m
    const int wn   = wid >> 2;         // 2 warp cols x 64 n
    const long blockM = (long)blockIdx.x * 128;

    const uint32_t as_base = (uint32_t)__cvta_generic_to_shared(As);
    const uint32_t bs_base = (uint32_t)__cvta_generic_to_shared(Bs);

    // ---- issue A chunk c (64 k-cols) into buffer c&1 via cp.async ----
    auto issue_chunk = [&](int c) {
        const float* src = (c < 2) ? Aagg : X;
        const int koff = (c & 1) * 64;
        const uint32_t sbase = as_base + (uint32_t)(c & 1) * (AS_WORDS * 4);
#pragma unroll
        for (int i = 0; i < 8; i++) {
            int idx = i * 256 + tid;
            int seg = idx & 15;                 // 16B segment in row
            int row = idx >> 4;
            const float* g = src + (blockM + row) * 128 + koff + seg * 4;
            cp_async16(sbase + row * (AS_STRIDE * 4) + seg * 16, g);
        }
        asm volatile("cp.async.commit_group;" ::);
    };

    issue_chunk(0);
    issue_chunk(1);

    // ---- stage B = [Wl ; Wr] (256 k x 128 n) as tf32, n-major rows ----
#pragma unroll
    for (int i = 0; i < 32; i++) {
        int idx = i * 256 + tid;
        int f4  = idx & 63;                     // k = f4*4, 0..255
        int n   = idx >> 6;
        int k   = f4 * 4;
        const float* wp = (k < 128) ? (Wl + n * 128 + k)
                                    : (Wr + n * 128 + (k - 128));
        float4 v = __ldg((const float4*)wp);
        uint32_t* d = Bs + n * BS_STRIDE + k;
        d[0] = f2tf32(v.x); d[1] = f2tf32(v.y);
        d[2] = f2tf32(v.z); d[3] = f2tf32(v.w);
    }

    float acc[2][8][4];
#pragma unroll
    for (int mi = 0; mi < 2; mi++)
#pragma unroll
        for (int ni = 0; ni < 8; ni++)
#pragma unroll
            for (int q = 0; q < 4; q++) acc[mi][ni][q] = 0.f;

    // precomputed fragment smem addresses (lane-dependent parts)
    // A: row = wm*32 + mi*16 + (lane&15), colsel = lane>>4 (x 16B)
    const uint32_t a_lane = (uint32_t)((wm * 32 + (lane & 15)) * (AS_STRIDE * 4)
                                       + (lane >> 4) * 16);
    // B: row n = wn*64 + ni*8 + (lane&7), colsel = (lane>>3)&1 (x 16B)
    const uint32_t b_lane = (uint32_t)((wn * 64 + (lane & 7)) * (BS_STRIDE * 4)
                                       + ((lane >> 3) & 1) * 16);

#pragma unroll 1
    for (int c = 0; c < 4; c++) {
        if (c < 3) asm volatile("cp.async.wait_group 1;" ::);
        else       asm volatile("cp.async.wait_group 0;" ::);
        __syncthreads();

        const uint32_t abuf = as_base + (uint32_t)(c & 1) * (AS_WORDS * 4);
#pragma unroll
        for (int kb = 0; kb < 64; kb += 8) {
            const int gk = c * 64 + kb;

            uint32_t bf[8][2];
#pragma unroll
            for (int ni = 0; ni < 8; ni++)
                ldsm_x2(bf[ni], bs_base + b_lane
                                + (uint32_t)(ni * 8 * BS_STRIDE * 4) + gk * 4);

            uint32_t af[2][4];
#pragma unroll
            for (int mi = 0; mi < 2; mi++) {
                ldsm_x4(af[mi], abuf + a_lane
                                + (uint32_t)(mi * 16 * AS_STRIDE * 4) + kb * 4);
#pragma unroll
                for (int q = 0; q < 4; q++)
                    asm volatile("cvt.rna.tf32.f32 %0, %0;" : "+r"(af[mi][q]));
            }

#pragma unroll
            for (int mi = 0; mi < 2; mi++)
#pragma unroll
                for (int ni = 0; ni < 8; ni++)
                    mma_tf32(acc[mi][ni], af[mi], bf[ni]);
        }
        __syncthreads();
        if (c + 2 < 4) issue_chunk(c + 2);
    }

    // ---- epilogue: float2 stores, optional ReLU ----
#pragma unroll
    for (int mi = 0; mi < 2; mi++) {
#pragma unroll
        for (int ni = 0; ni < 8; ni++) {
            long row = blockM + wm * 32 + mi * 16 + (lane >> 2);
            int  col = wn * 64 + ni * 8 + (lane & 3) * 2;
            float2 lo = make_float2(acc[mi][ni][0], acc[mi][ni][1]);
            float2 hi = make_float2(acc[mi][ni][2], acc[mi][ni][3]);
            if (relu) {
                lo.x = fmaxf(lo.x, 0.f); lo.y = fmaxf(lo.y, 0.f);
                hi.x = fmaxf(hi.x, 0.f); hi.y = fmaxf(hi.y, 0.f);
            }
            *(float2*)(out + row * 128 + col)       = lo;
            *(float2*)(out + (row + 8) * 128 + col) = hi;
        }
    }
}

// ---------------------------------------------------------------------------
// log_softmax over rows of [1024, 128]
// ---------------------------------------------------------------------------
__global__ void __launch_bounds__(256) lsm_kernel(
    const float* __restrict__ in, float* __restrict__ out)
{
    int row  = blockIdx.x * 8 + (threadIdx.x >> 5);
    int lane = threadIdx.x & 31;
    if (row >= N3_NODES) return;

    float4 v = reinterpret_cast<const float4*>(in)[(long)row * 32 + lane];

    float m = fmaxf(fmaxf(v.x, v.y), fmaxf(v.z, v.w));
#pragma unroll
    for (int o = 16; o > 0; o >>= 1)
        m = fmaxf(m, __shfl_xor_sync(0xFFFFFFFF, m, o));

    float s = expf(v.x - m) + expf(v.y - m) + expf(v.z - m) + expf(v.w - m);
#pragma unroll
    for (int o = 16; o > 0; o >>= 1)
        s += __shfl_xor_sync(0xFFFFFFFF, s, o);

    float lse = m + logf(s);
    float4 r = make_float4(v.x - lse, v.y - lse, v.z - lse, v.w - lse);
    reinterpret_cast<float4*>(out)[(long)row * 32 + lane] = r;
}

// ---------------------------------------------------------------------------
// Launch
// ---------------------------------------------------------------------------
extern "C" void kernel_launch(void* const* d_in, const int* in_sizes, int n_in,
                              void* d_out, int out_size)
{
    const long X_SZ = (long)N0_NODES * D;
    const int  W_SZ = D * D;

    const float* x = nullptr;
    const float* Wl[3] = {nullptr, nullptr, nullptr};
    const float* Wr[3] = {nullptr, nullptr, nullptr};
    const int*   src[3] = {nullptr, nullptr, nullptr};

    if ((long)in_sizes[0] == X_SZ && in_sizes[1] == W_SZ) {
        x = (const float*)d_in[0];
        for (int i = 0; i < 3; i++) {
            Wl[i]  = (const float*)d_in[1 + 2 * i];
            Wr[i]  = (const float*)d_in[2 + 2 * i];
            src[i] = (const int*)  d_in[7 + 2 * i];
        }
    } else if ((long)in_sizes[0] == X_SZ) {
        x = (const float*)d_in[0];
        for (int i = 0; i < 3; i++) {
            src[i] = (const int*)  d_in[1 + 4 * i];
            Wl[i]  = (const float*)d_in[3 + 4 * i];
            Wr[i]  = (const float*)d_in[4 + 4 * i];
        }
    } else {
        for (int i = 0; i < 3; i++) {
            Wl[i]  = (const float*)d_in[i];
            Wr[i]  = (const float*)d_in[3 + i];
            src[i] = (const int*)  d_in[9 + i];
        }
        x = (const float*)d_in[12];
    }

    float *agg, *h1, *h2, *logits;
    cudaGetSymbolAddress((void**)&agg,    g_agg);
    cudaGetSymbolAddress((void**)&h1,     g_h1);
    cudaGetSymbolAddress((void**)&h2,     g_h2);
    cudaGetSymbolAddress((void**)&logits, g_logits);

    cudaFuncSetAttribute(gemm_dual_kernel,
                         cudaFuncAttributeMaxDynamicSharedMemorySize,
                         GEMM_SMEM_BYTES);

    float* out = (float*)d_out;

    // Layer 0: N0 -> N1
    agg_kernel<F0><<<N1_NODES / 8, 256>>>(x, src[0], agg, N1_NODES);
    gemm_dual_kernel<<<N1_NODES / 128, 256, GEMM_SMEM_BYTES>>>(
        agg, x, Wl[0], Wr[0], h1, 1);

    // Layer 1: N1 -> N2
    agg_kernel<F1><<<N2_NODES / 8, 256>>>(h1, src[1], agg, N2_NODES);
    gemm_dual_kernel<<<N2_NODES / 128, 256, GEMM_SMEM_BYTES>>>(
        agg, h1, Wl[1], Wr[1], h2, 1);

    // Layer 2: N2 -> N3
    agg_kernel<F2><<<N3_NODES / 8, 256>>>(h2, src[2], agg, N3_NODES);
    gemm_dual_kernel<<<N3_NODES / 128, 256, GEMM_SMEM_BYTES>>>(
        agg, h2, Wl[2], Wr[2], logits, 0);

    // log_softmax
    lsm_kernel<<<N3_NODES / 8, 256>>>(logits, out);
}